// round 3
// baseline (speedup 1.0000x reference)
#include <cuda_runtime.h>

// Hierarchical softmax CE loss — quad-per-row coalesced gather, single fused kernel.
// Tree: OFFSET=[0,10,110,1110]; every sibling group = 10 contiguous nodes, even base.
// target leaf l: groups/sel: [0,10)@a0=l/100 ; [10+10a0,+10)@(j-10a0), j=l/10 ;
// [110+10j,+10)@(l-10j).  loss = -mean_b sum_path w[node]*logsoftmax_in_group.

#define BATCH   65536
#define NNODES  1110
#define TPB     256
#define RPB     (TPB / 4)          // 64 rows per block
#define NBLOCKS (BATCH / RPB)      // 1024

__device__ float    g_partials[NBLOCKS];
__device__ unsigned g_ticket = 0;

__global__ void __launch_bounds__(TPB)
hsm_quad_kernel(const float* __restrict__ x,
                const float* __restrict__ w,
                const int* __restrict__ target,
                float* __restrict__ out) {
    const int tid  = threadIdx.x;
    const int k    = tid & 3;                       // lane within quad
    const int row  = blockIdx.x * RPB + (tid >> 2);
    const float* xr = x + (size_t)row * NNODES;

    const int l  = __ldg(target + row);
    const int j  = l / 10;
    const int a0 = l / 100;

    const int base0 = 0,            loc0 = a0;
    const int base1 = 10 + 10 * a0, loc1 = j - 10 * a0;
    const int base2 = 110 + 10 * j, loc2 = l - 10 * j;

    float acc = 0.0f;
    const float NEG = -3.0e38f;

    const int bases[3] = {base0, base1, base2};
    const int locs[3]  = {loc0, loc1, loc2};

#pragma unroll
    for (int s3 = 0; s3 < 3; s3++) {
        const int base  = bases[s3];
        const int loc   = locs[s3];
        const int d     = base & 3;                 // 0 or 2 (base is even)
        const int start = base - d;                 // 16-float aligned window in row

        // lane k owns window floats [4k, 4k+4): two 8B-aligned float2 loads
        const float2* q = reinterpret_cast<const float2*>(xr + start);
        float2 p0 = __ldg(q + 2 * k);
        float2 p1 = __ldg(q + 2 * k + 1);
        const int off = 4 * k;
        // mask floats outside [d, d+10) to -huge (exp underflows to exactly 0)
        float v0 = (off + 0 >= d && off + 0 < d + 10) ? p0.x : NEG;
        float v1 = (off + 1 >= d && off + 1 < d + 10) ? p0.y : NEG;
        float v2 = (off + 2 >= d && off + 2 < d + 10) ? p1.x : NEG;
        float v3 = (off + 3 >= d && off + 3 < d + 10) ? p1.y : NEG;

        // quad max
        float m = fmaxf(fmaxf(v0, v1), fmaxf(v2, v3));
        m = fmaxf(m, __shfl_xor_sync(0xFFFFFFFFu, m, 1));
        m = fmaxf(m, __shfl_xor_sync(0xFFFFFFFFu, m, 2));

        // quad sum of exp (masked lanes contribute exact 0 via underflow)
        float s = expf(v0 - m) + expf(v1 - m) + expf(v2 - m) + expf(v3 - m);
        s += __shfl_xor_sync(0xFFFFFFFFu, s, 1);
        s += __shfl_xor_sync(0xFFFFFFFFu, s, 2);

        // only the lane owning the selected node adds the weighted term
        const int sel = d + loc;                    // window offset of selected node
        if ((sel >> 2) == k) {
            const int i = sel & 3;
            float xv = (i == 0) ? v0 : (i == 1) ? v1 : (i == 2) ? v2 : v3;
            acc += __ldg(w + base + loc) * (xv - m - logf(s));
        }
    }

    // ---- deterministic block reduction ----
    __shared__ float sm[TPB];
    sm[tid] = acc;
    __syncthreads();
#pragma unroll
    for (int s = TPB / 2; s > 32; s >>= 1) {
        if (tid < s) sm[tid] += sm[tid + s];
        __syncthreads();
    }
    __shared__ bool s_last;
    if (tid < 32) {
        float v = sm[tid] + sm[tid + 32];
#pragma unroll
        for (int o = 16; o > 0; o >>= 1)
            v += __shfl_down_sync(0xFFFFFFFFu, v, o);
        if (tid == 0) {
            g_partials[blockIdx.x] = v;
            __threadfence();
            unsigned t = atomicAdd(&g_ticket, 1u);
            s_last = (t == NBLOCKS - 1);
        }
    }
    __syncthreads();

    // ---- last block: deterministic fixed-order sum of 1024 partials ----
    if (s_last) {
        float v = 0.0f;
#pragma unroll
        for (int kk = 0; kk < NBLOCKS / TPB; kk++)   // 4 per thread
            v += g_partials[tid + kk * TPB];
        sm[tid] = v;
        __syncthreads();
#pragma unroll
        for (int s = TPB / 2; s > 32; s >>= 1) {
            if (tid < s) sm[tid] += sm[tid + s];
            __syncthreads();
        }
        if (tid < 32) {
            float r = sm[tid] + sm[tid + 32];
#pragma unroll
            for (int o = 16; o > 0; o >>= 1)
                r += __shfl_down_sync(0xFFFFFFFFu, r, o);
            if (tid == 0) {
                out[0] = -r / (float)BATCH;
                g_ticket = 0;                        // reset for next graph replay
            }
        }
    }
}

extern "C" void kernel_launch(void* const* d_in, const int* in_sizes, int n_in,
                              void* d_out, int out_size) {
    const float* x      = (const float*)d_in[0];
    const float* w      = (const float*)d_in[1];
    const int*   target = (const int*)d_in[2];
    float* out = (float*)d_out;

    hsm_quad_kernel<<<NBLOCKS, TPB>>>(x, w, target, out);
}